// round 9
// baseline (speedup 1.0000x reference)
#include <cuda_runtime.h>
#include <math.h>

#define BATCH 16
#define NCLS  20
#define NGT   64
#define N3    16384
#define N4    4096
#define N5    1024
#define NTOT  (N3 + N4 + N5)     // 21504
#define SEG   (NTOT / 32)        // 672 elements per warp segment
#define NIT   (SEG / 32)         // 21 iterations per warp
#define TOPK  1000
#define MAXDET 100
#define SCORE_THR 0.3f
#define IOU_THR   0.5f
#define NBIN  4096
#define TB0   0x3E99999Au        // float bits of 0.3f
#define SUPSTRIDE 1033           // bank-conflict-free transposed stride

// ---------------- scratch (device globals; zero-initialized at load) --------
__device__ float        g_scores[BATCH * NTOT];
__device__ float4       g_boxes [BATCH * NTOT];
__device__ int          g_cls   [BATCH * NTOT];
__device__ __align__(16) unsigned int g_hist[BATCH * NBIN]; // zeroed by k_post

__device__ __forceinline__ float sigmoidf_(float x) {
    if (x >= 0.f) return 1.f / (1.f + expf(-x));
    float e = expf(x);
    return e / (1.f + e);
}
__device__ __forceinline__ unsigned int fenc(float f) {
    unsigned int u = __float_as_uint(f);
    return (u & 0x80000000u) ? ~u : (u | 0x80000000u);
}
__device__ __forceinline__ float fdec(unsigned int e) {
    return (e & 0x80000000u) ? __uint_as_float(e & 0x7FFFFFFFu) : __uint_as_float(~e);
}

// =========== kernel 1: targets + score/decode + score histogram =============
__global__ __launch_bounds__(256) void k_fused(
    const float* __restrict__ l3, const float* __restrict__ l4, const float* __restrict__ l5,
    const float* __restrict__ gt,
    const float* __restrict__ c3, const float* __restrict__ c4, const float* __restrict__ c5,
    const float* __restrict__ r3, const float* __restrict__ r4, const float* __restrict__ r5,
    const float* __restrict__ t3, const float* __restrict__ t4, const float* __restrict__ t5,
    float4* __restrict__ od, float* __restrict__ oc)
{
    const int b   = blockIdx.y;
    const int tid = threadIdx.x;
    const int i   = blockIdx.x * 256 + tid;          // 84*256 == NTOT exactly

    __shared__ float4 sbox[NGT];
    __shared__ float  sarea[NGT];
    __shared__ int    swcnt[2];
    __shared__ int    scnt;

    float lower, upper, stride;
    if (blockIdx.x < 64)      { lower = 0.f;   upper = 64.f;     stride = 8.f;  }
    else if (blockIdx.x < 80) { lower = 64.f;  upper = 128.f;    stride = 16.f; }
    else                      { lower = 128.f; upper = INFINITY; stride = 32.f; }
    const float maxwh_hi = 2.0f * upper;

    // prefilter: maxd in (lower,upper) possible <=> max(w,h)>lower && max(w,h)/2<upper
    float x0 = 0.f, y0 = 0.f, x1 = 0.f, y1 = 0.f;
    bool  val = false;
    int   pref = 0;
    if (tid < 64) {
        const float* g = gt + (size_t)b * NGT * 5 + tid * 5;
        x0 = g[0]; y0 = g[1]; x1 = g[2]; y1 = g[3];
        float maxwh = fmaxf(x1 - x0, y1 - y0);
        val = (x0 >= 0.f) && (maxwh > lower) && (maxwh < maxwh_hi);
        int lane = tid & 31, w = tid >> 5;
        unsigned m = __ballot_sync(0xFFFFFFFFu, val);
        pref = __popc(m & ((1u << lane) - 1));
        if (lane == 0) swcnt[w] = __popc(m);
    }
    __syncthreads();
    if (tid < 64 && val) {
        int base = (tid >= 32) ? swcnt[0] : 0;
        int pos  = base + pref;
        sbox[pos]  = make_float4(x0, y0, x1, y1);
        sarea[pos] = (x1 - x0) * (y1 - y0);
    }
    if (tid == 0) scnt = swcnt[0] + swcnt[1];
    __syncthreads();

    int j, n;
    const float *locs, *cls, *reg, *ctr;
    if (i < N3)           { j = i;            n = N3; locs = l3; cls = c3; reg = r3; ctr = t3; }
    else if (i < N3 + N4) { j = i - N3;       n = N4; locs = l4; cls = c4; reg = r4; ctr = t4; }
    else                  { j = i - N3 - N4;  n = N5; locs = l5; cls = c5; reg = r5; ctr = t5; }
    float xc = locs[2*j], yc = locs[2*j+1];

    float bestA = INFINITY;
    int   besti = -1;
    const int nv = scnt;
    for (int m = 0; m < nv; m++) {
        float4 bb = sbox[m];
        float l = xc - bb.x, t = yc - bb.y, r = bb.z - xc, bo = bb.w - yc;
        float mn = fminf(fminf(l, t), fminf(r, bo));
        float mx = fmaxf(fmaxf(l, t), fmaxf(r, bo));
        float a  = sarea[m];
        if (mn > 0.f && mx > lower && mx < upper && a < bestA) { bestA = a; besti = m; }
    }

    float d0, d1, d2, d3, ctrt;
    if (besti < 0) {
        d0 = d1 = d2 = d3 = -1.f; ctrt = -1.f;
    } else {
        float4 bb = sbox[besti];
        d0 = (xc - bb.x) / stride;
        d1 = (yc - bb.y) / stride;
        d2 = (bb.z - xc) / stride;
        d3 = (bb.w - yc) / stride;
        float num = fminf(d0, d2) * fminf(d1, d3);
        float den = fmaxf(d0, d2) * fmaxf(d1, d3);
        ctrt = sqrtf(num / den);
    }
    size_t base = (size_t)(b * NTOT + i);
    od[base] = make_float4(d0, d1, d2, d3);
    oc[base] = ctrt;

    const float4* cp4 = reinterpret_cast<const float4*>(cls + ((size_t)b * n + j) * NCLS);
    float best = -INFINITY; int bc = 0;
    #pragma unroll
    for (int c4i = 0; c4i < 5; c4i++) {
        float4 v = cp4[c4i];
        if (v.x > best) { best = v.x; bc = c4i*4+0; }
        if (v.y > best) { best = v.y; bc = c4i*4+1; }
        if (v.z > best) { best = v.z; bc = c4i*4+2; }
        if (v.w > best) { best = v.w; bc = c4i*4+3; }
    }
    float sc = sqrtf(sigmoidf_(best) * sigmoidf_(ctr[(size_t)b * n + j]));

    float4 rp = reinterpret_cast<const float4*>(reg)[(size_t)b * n + j];
    float e0 = fmaxf(rp.x, 0.f) * stride;
    float e1 = fmaxf(rp.y, 0.f) * stride;
    float e2 = fmaxf(rp.z, 0.f) * stride;
    float e3 = fmaxf(rp.w, 0.f) * stride;

    int o = b * NTOT + i;
    g_scores[o] = sc;
    g_boxes[o]  = make_float4(xc - e0, yc - e1, xc + e2, yc + e3);
    g_cls[o]    = bc;

    unsigned int sb = __float_as_uint(sc);
    if (sb > TB0) atomicAdd(&g_hist[b * NBIN + ((sb >> 13) & (NBIN-1))], 1u);
}

// ---- full symmetric sup matrix: all tiles tr<=tc over 32 warps -------------
__device__ __forceinline__ void sup_full(
    unsigned int* __restrict__ sup, const float4* __restrict__ nbox,
    const float* __restrict__ areas, int wid, int lane)
{
    // 528 tiles (tr<=tc, 32x32 tiling of 1024x1024), ~16.5 per warp
    for (int g = wid; g < 528; g += 32) {
        int tc = (int)((sqrtf(8.0f * (float)g + 1.0f) - 1.0f) * 0.5f);
        if (((tc * (tc + 1)) >> 1) > g) tc--;
        else if ((((tc + 1) * (tc + 2)) >> 1) <= g) tc++;
        int tr = g - ((tc * (tc + 1)) >> 1);

        int p = (tr << 5) + lane;
        float4 pb = nbox[p];
        float  pa = areas[p];
        unsigned bits = 0;
        int jb = tc << 5;
        #pragma unroll 8
        for (int jj = 0; jj < 32; ++jj) {
            float4 qb = nbox[jb + jj];         // uniform -> LDS broadcast
            float ar  = areas[jb + jj];
            float xx1 = fmaxf(pb.x, qb.x);
            float yy1 = fmaxf(pb.y, qb.y);
            float xx2 = fminf(pb.z, qb.z);
            float yy2 = fminf(pb.w, qb.w);
            float inter = fmaxf(xx2 - xx1, 0.f) * fmaxf(yy2 - yy1, 0.f);
            float uni   = pa + ar - inter;
            if ((inter > IOU_THR * uni) || (uni == 0.f)) bits |= (1u << jj); // NaN-safe
        }
        sup[tc * SUPSTRIDE + p] = bits;
        if (tr != tc) {                        // mirror via 32x32 bit transpose
            unsigned tw = 0;
            #pragma unroll
            for (int k2 = 0; k2 < 32; ++k2) {
                unsigned bb = __ballot_sync(0xFFFFFFFFu, (bits >> k2) & 1u);
                if (lane == k2) tw = bb;
            }
            sup[tr * SUPSTRIDE + ((tc << 5) + lane)] = tw;
        }
    }
}

// ---- single warp-serial greedy walk over full 1024 window (nv <= 1000) ----
__device__ __forceinline__ void walk(
    const unsigned int* __restrict__ sup, int nv,
    unsigned int* __restrict__ skeep, int lane)
{
    unsigned removed = 0, keepm = 0;
    int kept = 0;
    for (int w = 0; w < 32 && kept < MAXDET; ++w) {
        int base = w << 5;
        if (base >= nv) break;
        int lim = min(32, nv - base);
        unsigned vmask = (lim == 32) ? 0xFFFFFFFFu : ((1u << lim) - 1u);
        unsigned cur  = __shfl_sync(0xFFFFFFFFu, removed, w);
        unsigned cand = ~cur & vmask;
        while (cand && kept < MAXDET) {
            int bit = __ffs(cand) - 1;
            int p = base + bit;
            if (lane == w) keepm |= (1u << bit);
            ++kept;
            removed |= sup[lane * SUPSTRIDE + p];
            cur  = __shfl_sync(0xFFFFFFFFu, removed, w);
            cand = ~cur & vmask & (0xFFFFFFFEu << bit);
        }
    }
    skeep[lane] = keepm;
}

// =========== kernel 2: rank-scatter top-k + per-bin sort + full NMS =========
// dynamic smem (total 169088 B):
//   [0,132224)      sup (32 x 1033 words); aliases shist/suf/suf0
//   [132224,148608) keys[2048] u64
//   [148608,164992) nbox[1024] float4
//   [164992,169088) areas[1024] float
__global__ __launch_bounds__(1024) void k_post(float* __restrict__ dets)
{
    extern __shared__ unsigned char dyn[];
    unsigned int*       shist = (unsigned int*)dyn;              // [4096]
    unsigned int*       suf   = (unsigned int*)(dyn + 16384);    // [4096]
    unsigned int*       suf0  = (unsigned int*)(dyn + 32768);    // [4096]
    unsigned int*       sup   = (unsigned int*)dyn;              // NMS phase
    unsigned long long* keys  = (unsigned long long*)(dyn + 132224);
    float4*             nbox  = (float4*)(dyn + 148608);
    float*              areas = (float*)(dyn + 164992);

    __shared__ unsigned int wsum[32], wAbove[32], skeep[32];
    __shared__ unsigned int sMaxU;
    __shared__ int sB, sB2, sTotal, sCand, sAbove, sBig;

    const int b    = blockIdx.x;
    const int tid  = threadIdx.x;
    const int lane = tid & 31, wid = tid >> 5;
    const float* sc = g_scores + b * NTOT;

    // ---- phase 1: pull histogram (uint4), zero global copy for replay ----
    {
        uint4* gh = (uint4*)(g_hist + b * NBIN);
        uint4 v = gh[tid];
        ((uint4*)shist)[tid] = v;
        gh[tid] = make_uint4(0u, 0u, 0u, 0u);
    }
    if (tid == 0) {
        sB = 0; sB2 = 0; sCand = 0; sAbove = 0; sBig = 0; sMaxU = fenc(0.0f);
    }
    __syncthreads();

    // ---- phase 2: suffix scan -> threshold bin B + per-bin start slots ----
    unsigned s0 = shist[4*tid], s1 = shist[4*tid+1], s2 = shist[4*tid+2], s3 = shist[4*tid+3];
    unsigned st = s0 + s1 + s2 + s3;
    unsigned inc = st;
    #pragma unroll
    for (int off = 1; off < 32; off <<= 1) {
        unsigned v = __shfl_down_sync(0xFFFFFFFFu, inc, off);
        if (lane + off < 32) inc += v;
    }
    if (lane == 0) wsum[wid] = inc;
    __syncthreads();
    if (tid < 32) {
        unsigned v = wsum[tid], winc = v;
        #pragma unroll
        for (int off = 1; off < 32; off <<= 1) {
            unsigned u = __shfl_down_sync(0xFFFFFFFFu, winc, off);
            if (tid + off < 32) winc += u;
        }
        wAbove[tid] = winc - v;
        if (tid == 0) sTotal = (int)winc;
    }
    __syncthreads();
    {
        unsigned cum = wAbove[wid] + (inc - st);
        unsigned hh[4] = { s3, s2, s1, s0 };
        #pragma unroll
        for (int q = 0; q < 4; q++) {
            int bin = 4*tid + 3 - q;
            suf[bin]  = cum;
            suf0[bin] = cum;
            if (cum < TOPK && cum + hh[q] >= TOPK) {
                sB = bin; sCand = (int)(cum + hh[q]); sAbove = (int)cum;
            }
            cum += hh[q];
        }
    }
    __syncthreads();
    if (sTotal < TOPK) {
        if (tid == 0) sCand = sTotal;
        __syncthreads();
    }
    const int B = sB;
    int B2 = 0;

    // ---- rare refinement: boundary bin too fat for the 2048-key buffer ----
    if (sCand > 2040) {
        unsigned* h2 = (unsigned*)keys;
        for (int k = tid; k < 2048; k += 1024) h2[k] = 0;
        __syncthreads();
        for (int k = tid; k < NTOT; k += 1024) {
            unsigned bits = __float_as_uint(sc[k]);
            if (bits > TB0 && (int)((bits >> 13) & (NBIN-1)) == B)
                atomicAdd(&h2[(bits >> 2) & 2047u], 1u);
        }
        __syncthreads();
        if (tid == 0) {
            unsigned cum2 = (unsigned)sAbove; int bb = 0;
            for (int k = 2047; k >= 0; k--) {
                if (cum2 + h2[k] >= TOPK) { bb = k; break; }
                cum2 += h2[k];
            }
            sB2 = bb;
        }
        __syncthreads();
        B2 = sB2;
        __syncthreads();
    }

    // ---- phase 3: zero keys, then rank-scatter (front-batched loads) ----
    for (int k = tid; k < 2048; k += 1024) keys[k] = 0ull;
    __syncthreads();
    {
        unsigned bitsA[NIT];
        const float* segp = sc + wid * SEG + lane;
        #pragma unroll
        for (int it = 0; it < NIT; it++)
            bitsA[it] = __float_as_uint(segp[it * 32]);     // 21 independent LDGs
        #pragma unroll
        for (int it = 0; it < NIT; it++) {
            unsigned bits = bitsA[it];
            int k = wid * SEG + it * 32 + lane;
            int bin = (int)((bits >> 13) & (NBIN-1));
            bool cand = (bits > TB0) && (bin > B || (bin == B && (int)((bits >> 2) & 2047u) >= B2));
            if (cand) {
                unsigned pos = atomicAdd(&suf[bin], 1u);
                if (pos < 2048)
                    keys[pos] = ((unsigned long long)bits << 32)
                              | (unsigned long long)(0xFFFFFFFFu - (unsigned)k);
            }
        }
    }
    __syncthreads();

    // ---- phase 4: per-bin warp-local sort (descending) ----
    {
        bool big = false;
        for (int bin = B + wid; bin < NBIN; bin += 32) {
            unsigned start = min(suf0[bin], 2048u);
            unsigned end   = min(suf[bin],  2048u);
            int cnt = (int)(end - start);
            if (cnt >= 2) {
                if (cnt <= 32) {
                    unsigned long long k64 = (lane < cnt) ? keys[start + lane] : 0ull;
                    #pragma unroll
                    for (int sz = 2; sz <= 32; sz <<= 1) {
                        for (int off = sz >> 1; off > 0; off >>= 1) {
                            unsigned long long o = __shfl_xor_sync(0xFFFFFFFFu, k64, off);
                            bool lower2 = (lane & off) == 0;
                            bool ascb   = (lane & sz) != 0;
                            bool keepmax = lower2 ^ ascb;
                            bool gt = k64 > o;
                            k64 = (keepmax == gt) ? k64 : o;
                        }
                    }
                    if (lane < cnt) keys[start + lane] = k64;
                } else big = true;
            }
        }
        if (__ballot_sync(0xFFFFFFFFu, big) && lane == 0) sBig = 1;
    }
    __syncthreads();
    if (sBig) {   // fallback: full descending bitonic over 2048
        for (unsigned ksz = 2; ksz <= 2048; ksz <<= 1) {
            for (unsigned jj = ksz >> 1; jj > 0; jj >>= 1) {
                for (unsigned idx = tid; idx < 2048; idx += 1024) {
                    unsigned ixj = idx ^ jj;
                    if (ixj > idx) {
                        unsigned long long a = keys[idx], c = keys[ixj];
                        bool up = ((idx & ksz) == 0);
                        if (up ? (a < c) : (a > c)) { keys[idx] = c; keys[ixj] = a; }
                    }
                }
                if (jj >= 16) __syncthreads();
                else __syncwarp();
            }
            __syncthreads();
        }
    }

    // ---- phase 5: gather top-1000, max_coord, offset boxes ----
    unsigned long long key = (tid < TOPK) ? keys[tid] : 0ull;
    float s = __uint_as_float((unsigned)(key >> 32));
    unsigned gidx = 0xFFFFFFFFu - (unsigned)key;
    bool valid = (tid < TOPK) && (key != 0ull);
    float4 bx = make_float4(0.f, 0.f, 0.f, 0.f);
    int cid = 0;
    if (valid) { bx = g_boxes[b * NTOT + gidx]; cid = g_cls[b * NTOT + gidx]; }
    float mrow = valid ? fmaxf(fmaxf(bx.x, bx.y), fmaxf(bx.z, bx.w)) : 0.f;
    {
        unsigned e = fenc(mrow);
        #pragma unroll
        for (int off = 16; off > 0; off >>= 1)
            e = max(e, __shfl_down_sync(0xFFFFFFFFu, e, off));
        if (lane == 0) atomicMax(&sMaxU, e);
    }
    int NVraw = __syncthreads_count(valid);
    const int NV = min(NVraw, TOPK);
    const float offmul = fdec(sMaxU) + 1.0f;
    if (tid < TOPK) {
        float o = (float)cid * offmul;
        float4 nb = make_float4(bx.x + o, bx.y + o, bx.z + o, bx.w + o);
        nbox[tid]  = nb;
        areas[tid] = (nb.z - nb.x) * (nb.w - nb.y);
    } else if (tid < 1024) {
        nbox[tid]  = make_float4(0.f, 0.f, 0.f, 0.f);
        areas[tid] = 0.f;
    }
    __syncthreads();    // nbox/areas ready; sup may now overwrite shist/suf/suf0

    // ---- phase 6: full symmetric sup matrix + single walk ----
    sup_full(sup, nbox, areas, wid, lane);
    __syncthreads();
    if (wid == 0) walk(sup, NV, skeep, lane);
    __syncthreads();

    // ---- phase 7: write detections ----
    if (tid < TOPK) {
        float* det = dets + (size_t)b * TOPK * 5 + (size_t)tid * 5;
        if ((skeep[tid >> 5] >> (tid & 31)) & 1u) {
            det[0] = bx.x; det[1] = bx.y; det[2] = bx.z; det[3] = bx.w; det[4] = s;
        } else {
            det[0] = 0.f; det[1] = 0.f; det[2] = 0.f; det[3] = 0.f; det[4] = 0.f;
        }
    }
}

// ---------------- launch ----------------------------------------------------
extern "C" void kernel_launch(void* const* d_in, const int* in_sizes, int n_in,
                              void* d_out, int out_size)
{
    const float* l3 = (const float*)d_in[0];
    const float* l4 = (const float*)d_in[1];
    const float* l5 = (const float*)d_in[2];
    const float* gt = (const float*)d_in[3];

    const float *c3, *c4, *c5, *r3, *r4, *r5, *t3, *t4, *t5;
    if (in_sizes[5] == BATCH * N3 * 4) {
        c3 = (const float*)d_in[4];  r3 = (const float*)d_in[5];  t3 = (const float*)d_in[6];
        c4 = (const float*)d_in[7];  r4 = (const float*)d_in[8];  t4 = (const float*)d_in[9];
        c5 = (const float*)d_in[10]; r5 = (const float*)d_in[11]; t5 = (const float*)d_in[12];
    } else {
        c3 = (const float*)d_in[4];  c4 = (const float*)d_in[5];  c5 = (const float*)d_in[6];
        r3 = (const float*)d_in[7];  r4 = (const float*)d_in[8];  r5 = (const float*)d_in[9];
        t3 = (const float*)d_in[10]; t4 = (const float*)d_in[11]; t5 = (const float*)d_in[12];
    }

    float* out       = (float*)d_out;
    float* out_dets  = out;                                   // [16,1000,5]
    float* out_delta = out + (size_t)BATCH * TOPK * 5;        // [16,21504,4]
    float* out_ctr   = out_delta + (size_t)BATCH * NTOT * 4;  // [16,21504]

    const int post_smem = 169088;
    cudaFuncSetAttribute(k_post, cudaFuncAttributeMaxDynamicSharedMemorySize, post_smem);

    dim3 grd(NTOT / 256, BATCH);
    k_fused<<<grd, 256>>>(l3, l4, l5, gt, c3, c4, c5, r3, r4, r5, t3, t4, t5,
                          (float4*)out_delta, out_ctr);
    k_post <<<BATCH, 1024, post_smem>>>(out_dets);
}

// round 10
// speedup vs baseline: 2.9617x; 2.9617x over previous
#include <cuda_runtime.h>
#include <math.h>

#define BATCH 16
#define NCLS  20
#define NGT   64
#define N3    16384
#define N4    4096
#define N5    1024
#define NTOT  (N3 + N4 + N5)     // 21504
#define SEG   (NTOT / 32)        // 672 elements per warp segment
#define NIT   (SEG / 32)         // 21 iterations per warp
#define TOPK  1000
#define MAXDET 100
#define SCORE_THR 0.3f
#define IOU_THR   0.5f
#define NBIN  4096
#define BINHI 3072               // scores < 1.0 => occupied bins < 3072
#define TB0   0x3E99999Au        // float bits of 0.3f
#define SUPSTRIDE 1033           // bank-conflict-free transposed stride

// ---------------- scratch (device globals; zero-initialized at load) --------
__device__ float        g_scores[BATCH * NTOT];
__device__ float4       g_boxes [BATCH * NTOT];
__device__ int          g_cls   [BATCH * NTOT];
__device__ __align__(16) unsigned int g_hist[BATCH * NBIN]; // zeroed by k_post

__device__ __forceinline__ float sigmoidf_(float x) {
    if (x >= 0.f) return 1.f / (1.f + expf(-x));
    float e = expf(x);
    return e / (1.f + e);
}
__device__ __forceinline__ unsigned int fenc(float f) {
    unsigned int u = __float_as_uint(f);
    return (u & 0x80000000u) ? ~u : (u | 0x80000000u);
}
__device__ __forceinline__ float fdec(unsigned int e) {
    return (e & 0x80000000u) ? __uint_as_float(e & 0x7FFFFFFFu) : __uint_as_float(~e);
}

// =========== kernel 1: targets + score/decode + score histogram =============
__global__ __launch_bounds__(256) void k_fused(
    const float* __restrict__ l3, const float* __restrict__ l4, const float* __restrict__ l5,
    const float* __restrict__ gt,
    const float* __restrict__ c3, const float* __restrict__ c4, const float* __restrict__ c5,
    const float* __restrict__ r3, const float* __restrict__ r4, const float* __restrict__ r5,
    const float* __restrict__ t3, const float* __restrict__ t4, const float* __restrict__ t5,
    float4* __restrict__ od, float* __restrict__ oc)
{
    const int b   = blockIdx.y;
    const int tid = threadIdx.x;
    const int i   = blockIdx.x * 256 + tid;          // 84*256 == NTOT exactly

    __shared__ float4 sbox[NGT];
    __shared__ float  sarea[NGT];
    __shared__ int    swcnt[2];
    __shared__ int    scnt;

    float lower, upper, stride;
    if (blockIdx.x < 64)      { lower = 0.f;   upper = 64.f;     stride = 8.f;  }
    else if (blockIdx.x < 80) { lower = 64.f;  upper = 128.f;    stride = 16.f; }
    else                      { lower = 128.f; upper = INFINITY; stride = 32.f; }
    const float maxwh_hi = 2.0f * upper;

    // prefilter: maxd in (lower,upper) possible <=> max(w,h)>lower && max(w,h)/2<upper
    float x0 = 0.f, y0 = 0.f, x1 = 0.f, y1 = 0.f;
    bool  val = false;
    int   pref = 0;
    if (tid < 64) {
        const float* g = gt + (size_t)b * NGT * 5 + tid * 5;
        x0 = g[0]; y0 = g[1]; x1 = g[2]; y1 = g[3];
        float maxwh = fmaxf(x1 - x0, y1 - y0);
        val = (x0 >= 0.f) && (maxwh > lower) && (maxwh < maxwh_hi);
        int lane = tid & 31, w = tid >> 5;
        unsigned m = __ballot_sync(0xFFFFFFFFu, val);
        pref = __popc(m & ((1u << lane) - 1));
        if (lane == 0) swcnt[w] = __popc(m);
    }
    __syncthreads();
    if (tid < 64 && val) {
        int base = (tid >= 32) ? swcnt[0] : 0;
        int pos  = base + pref;
        sbox[pos]  = make_float4(x0, y0, x1, y1);
        sarea[pos] = (x1 - x0) * (y1 - y0);
    }
    if (tid == 0) scnt = swcnt[0] + swcnt[1];
    __syncthreads();

    int j, n;
    const float *locs, *cls, *reg, *ctr;
    if (i < N3)           { j = i;            n = N3; locs = l3; cls = c3; reg = r3; ctr = t3; }
    else if (i < N3 + N4) { j = i - N3;       n = N4; locs = l4; cls = c4; reg = r4; ctr = t4; }
    else                  { j = i - N3 - N4;  n = N5; locs = l5; cls = c5; reg = r5; ctr = t5; }
    float xc = locs[2*j], yc = locs[2*j+1];

    float bestA = INFINITY;
    int   besti = -1;
    const int nv = scnt;
    for (int m = 0; m < nv; m++) {
        float4 bb = sbox[m];
        float l = xc - bb.x, t = yc - bb.y, r = bb.z - xc, bo = bb.w - yc;
        float mn = fminf(fminf(l, t), fminf(r, bo));
        float mx = fmaxf(fmaxf(l, t), fmaxf(r, bo));
        float a  = sarea[m];
        if (mn > 0.f && mx > lower && mx < upper && a < bestA) { bestA = a; besti = m; }
    }

    float d0, d1, d2, d3, ctrt;
    if (besti < 0) {
        d0 = d1 = d2 = d3 = -1.f; ctrt = -1.f;
    } else {
        float4 bb = sbox[besti];
        d0 = (xc - bb.x) / stride;
        d1 = (yc - bb.y) / stride;
        d2 = (bb.z - xc) / stride;
        d3 = (bb.w - yc) / stride;
        float num = fminf(d0, d2) * fminf(d1, d3);
        float den = fmaxf(d0, d2) * fmaxf(d1, d3);
        ctrt = sqrtf(num / den);
    }
    size_t base = (size_t)(b * NTOT + i);
    od[base] = make_float4(d0, d1, d2, d3);
    oc[base] = ctrt;

    const float4* cp4 = reinterpret_cast<const float4*>(cls + ((size_t)b * n + j) * NCLS);
    float best = -INFINITY; int bc = 0;
    #pragma unroll
    for (int c4i = 0; c4i < 5; c4i++) {
        float4 v = cp4[c4i];
        if (v.x > best) { best = v.x; bc = c4i*4+0; }
        if (v.y > best) { best = v.y; bc = c4i*4+1; }
        if (v.z > best) { best = v.z; bc = c4i*4+2; }
        if (v.w > best) { best = v.w; bc = c4i*4+3; }
    }
    float sc = sqrtf(sigmoidf_(best) * sigmoidf_(ctr[(size_t)b * n + j]));

    float4 rp = reinterpret_cast<const float4*>(reg)[(size_t)b * n + j];
    float e0 = fmaxf(rp.x, 0.f) * stride;
    float e1 = fmaxf(rp.y, 0.f) * stride;
    float e2 = fmaxf(rp.z, 0.f) * stride;
    float e3 = fmaxf(rp.w, 0.f) * stride;

    int o = b * NTOT + i;
    g_scores[o] = sc;
    g_boxes[o]  = make_float4(xc - e0, yc - e1, xc + e2, yc + e3);
    g_cls[o]    = bc;

    unsigned int sb = __float_as_uint(sc);
    if (sb > TB0) atomicAdd(&g_hist[b * NBIN + ((sb >> 13) & (NBIN-1))], 1u);
}

// ---- warp-register bitonic sort of 32 u64, descending ----------------------
__device__ __forceinline__ unsigned long long warp_sort32_desc(
    unsigned long long k64, int lane)
{
    #pragma unroll
    for (int sz = 2; sz <= 32; sz <<= 1) {
        for (int off = sz >> 1; off > 0; off >>= 1) {
            unsigned long long o = __shfl_xor_sync(0xFFFFFFFFu, k64, off);
            bool lower2 = (lane & off) == 0;
            bool ascb   = (lane & sz) != 0;
            bool keepmax = lower2 ^ ascb;
            bool gt = k64 > o;
            k64 = (keepmax == gt) ? k64 : o;
        }
    }
    return k64;   // lane r holds rank-r (descending)
}

// ---- symmetric sup band: tiles tr<=tc, tc in [Ts,Tn) ----------------------
__device__ __forceinline__ void sup_band(
    unsigned int* __restrict__ sup, const float4* __restrict__ nbox,
    const float* __restrict__ areas, int Ts, int Tn, int wid, int lane)
{
    const int g0 = (Ts * (Ts + 1)) >> 1;
    const int g1 = (Tn * (Tn + 1)) >> 1;
    for (int g = g0 + wid; g < g1; g += 32) {
        int tc = (int)((sqrtf(8.0f * (float)g + 1.0f) - 1.0f) * 0.5f);
        if (((tc * (tc + 1)) >> 1) > g) tc--;
        else if ((((tc + 1) * (tc + 2)) >> 1) <= g) tc++;
        int tr = g - ((tc * (tc + 1)) >> 1);

        int p = (tr << 5) + lane;
        float4 pb = nbox[p];
        float  pa = areas[p];
        unsigned bits = 0;
        int jb = tc << 5;
        #pragma unroll 8
        for (int jj = 0; jj < 32; ++jj) {
            float4 qb = nbox[jb + jj];
            float ar  = areas[jb + jj];
            float xx1 = fmaxf(pb.x, qb.x);
            float yy1 = fmaxf(pb.y, qb.y);
            float xx2 = fminf(pb.z, qb.z);
            float yy2 = fminf(pb.w, qb.w);
            float inter = fmaxf(xx2 - xx1, 0.f) * fmaxf(yy2 - yy1, 0.f);
            float uni   = pa + ar - inter;
            if ((inter > IOU_THR * uni) || (uni == 0.f)) bits |= (1u << jj);
        }
        sup[tc * SUPSTRIDE + p] = bits;
        if (tr != tc) {
            unsigned tw = 0;
            #pragma unroll
            for (int k2 = 0; k2 < 32; ++k2) {
                unsigned bb = __ballot_sync(0xFFFFFFFFu, (bits >> k2) & 1u);
                if (lane == k2) tw = bb;
            }
            sup[tr * SUPSTRIDE + ((tc << 5) + lane)] = tw;
        }
    }
}

// ---- warp-serial greedy walk over sorted order (ffs jumping) ----
__device__ __forceinline__ void walk(
    const unsigned int* __restrict__ sup, int nv, int L,
    unsigned int* __restrict__ skeep, int* __restrict__ esc, int lane)
{
    unsigned removed = 0, keepm = 0;
    int kept = 0; bool bad = false;
    for (int w = 0; w < 32 && kept < MAXDET; ++w) {
        int base = w << 5;
        if (base >= nv) break;
        if (base >= L) { bad = true; break; }
        int lim = min(32, nv - base);
        unsigned vmask = (lim == 32) ? 0xFFFFFFFFu : ((1u << lim) - 1u);
        unsigned cur  = __shfl_sync(0xFFFFFFFFu, removed, w);
        unsigned cand = ~cur & vmask;
        while (cand && kept < MAXDET) {
            int bit = __ffs(cand) - 1;
            int p = base + bit;
            if (lane == w) keepm |= (1u << bit);
            ++kept;
            removed |= sup[lane * SUPSTRIDE + p];
            cur  = __shfl_sync(0xFFFFFFFFu, removed, w);
            cand = ~cur & vmask & (0xFFFFFFFEu << bit);
        }
    }
    skeep[lane] = keepm;
    if (lane == 0 && bad) *esc = 1;
}

// =========== kernel 2: rank-scatter top-k + per-bin sort + ladder NMS =======
// dynamic smem (total 169088 B):
//   [0,132224)      sup (32 x 1033 words); aliases shist/suf/suf0
//   [132224,148608) keys[2048] u64
//   [148608,164992) nbox[1024] float4
//   [164992,169088) areas[1024] float
__global__ __launch_bounds__(1024) void k_post(float* __restrict__ dets)
{
    extern __shared__ unsigned char dyn[];
    unsigned int*       shist = (unsigned int*)dyn;              // [4096]
    unsigned int*       suf   = (unsigned int*)(dyn + 16384);    // [4096]
    unsigned int*       suf0  = (unsigned int*)(dyn + 32768);    // [4096]
    unsigned int*       sup   = (unsigned int*)dyn;              // NMS phase
    unsigned long long* keys  = (unsigned long long*)(dyn + 132224);
    float4*             nbox  = (float4*)(dyn + 148608);
    float*              areas = (float*)(dyn + 164992);

    __shared__ unsigned int wsum[32], wAbove[32], skeep[32];
    __shared__ unsigned int sMaxU;
    __shared__ int sB, sB2, sTotal, sCand, sAbove, sBig;
    __shared__ int sEsc1, sEsc2, sEsc3, sEsc4;

    const int b    = blockIdx.x;
    const int tid  = threadIdx.x;
    const int lane = tid & 31, wid = tid >> 5;
    const float* sc = g_scores + b * NTOT;

    // ---- phase 1: pull histogram (uint4), zero global copy for replay ----
    {
        uint4* gh = (uint4*)(g_hist + b * NBIN);
        uint4 v = gh[tid];
        ((uint4*)shist)[tid] = v;
        gh[tid] = make_uint4(0u, 0u, 0u, 0u);
    }
    if (tid == 0) {
        sB = 0; sB2 = 0; sCand = 0; sAbove = 0; sBig = 0;
        sEsc1 = 0; sEsc2 = 0; sEsc3 = 0; sEsc4 = 0; sMaxU = fenc(0.0f);
    }
    __syncthreads();

    // ---- phase 2: suffix scan -> threshold bin B + per-bin start slots ----
    unsigned s0 = shist[4*tid], s1 = shist[4*tid+1], s2 = shist[4*tid+2], s3 = shist[4*tid+3];
    unsigned st = s0 + s1 + s2 + s3;
    unsigned inc = st;
    #pragma unroll
    for (int off = 1; off < 32; off <<= 1) {
        unsigned v = __shfl_down_sync(0xFFFFFFFFu, inc, off);
        if (lane + off < 32) inc += v;
    }
    if (lane == 0) wsum[wid] = inc;
    __syncthreads();
    if (tid < 32) {
        unsigned v = wsum[tid], winc = v;
        #pragma unroll
        for (int off = 1; off < 32; off <<= 1) {
            unsigned u = __shfl_down_sync(0xFFFFFFFFu, winc, off);
            if (tid + off < 32) winc += u;
        }
        wAbove[tid] = winc - v;
        if (tid == 0) sTotal = (int)winc;
    }
    __syncthreads();
    {
        unsigned cum = wAbove[wid] + (inc - st);
        unsigned hh[4] = { s3, s2, s1, s0 };
        #pragma unroll
        for (int q = 0; q < 4; q++) {
            int bin = 4*tid + 3 - q;
            suf[bin]  = cum;
            suf0[bin] = cum;
            if (cum < TOPK && cum + hh[q] >= TOPK) {
                sB = bin; sCand = (int)(cum + hh[q]); sAbove = (int)cum;
            }
            cum += hh[q];
        }
    }
    __syncthreads();
    if (sTotal < TOPK) {
        if (tid == 0) sCand = sTotal;
        __syncthreads();
    }
    const int B = sB;
    int B2 = 0;

    // ---- rare refinement: boundary bin too fat for the 2048-key buffer ----
    if (sCand > 2040) {
        unsigned* h2 = (unsigned*)keys;
        for (int k = tid; k < 2048; k += 1024) h2[k] = 0;
        __syncthreads();
        for (int k = tid; k < NTOT; k += 1024) {
            unsigned bits = __float_as_uint(sc[k]);
            if (bits > TB0 && (int)((bits >> 13) & (NBIN-1)) == B)
                atomicAdd(&h2[(bits >> 2) & 2047u], 1u);
        }
        __syncthreads();
        if (tid == 0) {
            unsigned cum2 = (unsigned)sAbove; int bb = 0;
            for (int k = 2047; k >= 0; k--) {
                if (cum2 + h2[k] >= TOPK) { bb = k; break; }
                cum2 += h2[k];
            }
            sB2 = bb;
        }
        __syncthreads();
        B2 = sB2;
        __syncthreads();
    }

    // ---- phase 3: zero keys, then rank-scatter (front-batched loads) ----
    for (int k = tid; k < 2048; k += 1024) keys[k] = 0ull;
    __syncthreads();
    {
        unsigned bitsA[NIT];
        const float* segp = sc + wid * SEG + lane;
        #pragma unroll
        for (int it = 0; it < NIT; it++)
            bitsA[it] = __float_as_uint(segp[it * 32]);
        #pragma unroll
        for (int it = 0; it < NIT; it++) {
            unsigned bits = bitsA[it];
            int k = wid * SEG + it * 32 + lane;
            int bin = (int)((bits >> 13) & (NBIN-1));
            bool cand = (bits > TB0) && (bin > B || (bin == B && (int)((bits >> 2) & 2047u) >= B2));
            if (cand) {
                unsigned pos = atomicAdd(&suf[bin], 1u);
                if (pos < 2048)
                    keys[pos] = ((unsigned long long)bits << 32)
                              | (unsigned long long)(0xFFFFFFFFu - (unsigned)k);
            }
        }
    }
    __syncthreads();

    // ---- phase 4: per-bin warp-local sort, cnt<=64 handled in registers ----
    {
        bool big = false;
        for (int bin = B + wid; bin < BINHI; bin += 32) {
            unsigned start = min(suf0[bin], 2048u);
            unsigned end   = min(suf[bin],  2048u);
            int cnt = (int)(end - start);
            if (cnt >= 2) {
                if (cnt <= 32) {
                    unsigned long long a = (lane < cnt) ? keys[start + lane] : 0ull;
                    a = warp_sort32_desc(a, lane);
                    if (lane < cnt) keys[start + lane] = a;
                } else if (cnt <= 64) {
                    // 64-element descending sort: two warp sorts + bitonic merge
                    unsigned long long a2 = keys[start + lane];   // lane<32<=cnt: in-range
                    unsigned long long b2 = (32 + lane < cnt) ? keys[start + 32 + lane] : 0ull;
                    a2 = warp_sort32_desc(a2, lane);
                    b2 = warp_sort32_desc(b2, lane);
                    b2 = __shfl_xor_sync(0xFFFFFFFFu, b2, 31);    // reverse -> ascending
                    // now (a2 desc | b2 asc) is bitonic; merge descending
                    {
                        unsigned long long hi = (a2 > b2) ? a2 : b2;
                        unsigned long long lo = (a2 > b2) ? b2 : a2;
                        a2 = hi; b2 = lo;
                    }
                    #pragma unroll
                    for (int off = 16; off > 0; off >>= 1) {
                        bool lower2 = (lane & off) == 0;
                        unsigned long long oa = __shfl_xor_sync(0xFFFFFFFFu, a2, off);
                        bool gta = a2 > oa;
                        a2 = (lower2 == gta) ? a2 : oa;
                        unsigned long long ob = __shfl_xor_sync(0xFFFFFFFFu, b2, off);
                        bool gtb = b2 > ob;
                        b2 = (lower2 == gtb) ? b2 : ob;
                    }
                    keys[start + lane] = a2;                       // ranks 0..31
                    if (32 + lane < cnt) keys[start + 32 + lane] = b2;  // zeros sift to tail
                } else big = true;
            }
        }
        if (__ballot_sync(0xFFFFFFFFu, big) && lane == 0) sBig = 1;
    }
    __syncthreads();
    if (sBig) {   // fallback: full descending bitonic over 2048 (rare)
        for (unsigned ksz = 2; ksz <= 2048; ksz <<= 1) {
            for (unsigned jj = ksz >> 1; jj > 0; jj >>= 1) {
                for (unsigned idx = tid; idx < 2048; idx += 1024) {
                    unsigned ixj = idx ^ jj;
                    if (ixj > idx) {
                        unsigned long long a = keys[idx], c = keys[ixj];
                        bool up = ((idx & ksz) == 0);
                        if (up ? (a < c) : (a > c)) { keys[idx] = c; keys[ixj] = a; }
                    }
                }
                if (jj >= 16) __syncthreads();
                else __syncwarp();
            }
            __syncthreads();
        }
    }

    // ---- phase 5: gather top-1000, max_coord, offset boxes ----
    unsigned long long key = (tid < TOPK) ? keys[tid] : 0ull;
    float s = __uint_as_float((unsigned)(key >> 32));
    unsigned gidx = 0xFFFFFFFFu - (unsigned)key;
    bool valid = (tid < TOPK) && (key != 0ull);
    float4 bx = make_float4(0.f, 0.f, 0.f, 0.f);
    int cid = 0;
    if (valid) { bx = g_boxes[b * NTOT + gidx]; cid = g_cls[b * NTOT + gidx]; }
    float mrow = valid ? fmaxf(fmaxf(bx.x, bx.y), fmaxf(bx.z, bx.w)) : 0.f;
    {
        unsigned e = fenc(mrow);
        #pragma unroll
        for (int off = 16; off > 0; off >>= 1)
            e = max(e, __shfl_down_sync(0xFFFFFFFFu, e, off));
        if (lane == 0) atomicMax(&sMaxU, e);
    }
    int NVraw = __syncthreads_count(valid);
    const int NV = min(NVraw, TOPK);
    const float offmul = fdec(sMaxU) + 1.0f;
    if (tid < TOPK) {
        float o = (float)cid * offmul;
        float4 nb = make_float4(bx.x + o, bx.y + o, bx.z + o, bx.w + o);
        nbox[tid]  = nb;
        areas[tid] = (nb.z - nb.x) * (nb.w - nb.y);
    } else if (tid < 1024) {
        nbox[tid]  = make_float4(0.f, 0.f, 0.f, 0.f);
        areas[tid] = 0.f;
    }
    __syncthreads();    // nbox/areas ready; sup may now overwrite shist/suf/suf0

    // ---- phase 6: symmetric NMS ladder 256 -> 512 -> 768 -> 1024 ----
    sup_band(sup, nbox, areas, 0, 8, wid, lane);
    __syncthreads();
    if (tid < 32) walk(sup, NV, 256, skeep, &sEsc1, tid);
    __syncthreads();
    if (sEsc1) {
        sup_band(sup, nbox, areas, 8, 16, wid, lane);
        __syncthreads();
        if (tid < 32) walk(sup, NV, 512, skeep, &sEsc2, tid);
        __syncthreads();
        if (sEsc2) {
            sup_band(sup, nbox, areas, 16, 24, wid, lane);
            __syncthreads();
            if (tid < 32) walk(sup, NV, 768, skeep, &sEsc3, tid);
            __syncthreads();
            if (sEsc3) {
                sup_band(sup, nbox, areas, 24, 32, wid, lane);
                __syncthreads();
                if (tid < 32) walk(sup, NV, 1024, skeep, &sEsc4, tid);
                __syncthreads();
            }
        }
    }

    // ---- phase 7: write detections ----
    if (tid < TOPK) {
        float* det = dets + (size_t)b * TOPK * 5 + (size_t)tid * 5;
        if ((skeep[tid >> 5] >> (tid & 31)) & 1u) {
            det[0] = bx.x; det[1] = bx.y; det[2] = bx.z; det[3] = bx.w; det[4] = s;
        } else {
            det[0] = 0.f; det[1] = 0.f; det[2] = 0.f; det[3] = 0.f; det[4] = 0.f;
        }
    }
}

// ---------------- launch ----------------------------------------------------
extern "C" void kernel_launch(void* const* d_in, const int* in_sizes, int n_in,
                              void* d_out, int out_size)
{
    const float* l3 = (const float*)d_in[0];
    const float* l4 = (const float*)d_in[1];
    const float* l5 = (const float*)d_in[2];
    const float* gt = (const float*)d_in[3];

    const float *c3, *c4, *c5, *r3, *r4, *r5, *t3, *t4, *t5;
    if (in_sizes[5] == BATCH * N3 * 4) {
        c3 = (const float*)d_in[4];  r3 = (const float*)d_in[5];  t3 = (const float*)d_in[6];
        c4 = (const float*)d_in[7];  r4 = (const float*)d_in[8];  t4 = (const float*)d_in[9];
        c5 = (const float*)d_in[10]; r5 = (const float*)d_in[11]; t5 = (const float*)d_in[12];
    } else {
        c3 = (const float*)d_in[4];  c4 = (const float*)d_in[5];  c5 = (const float*)d_in[6];
        r3 = (const float*)d_in[7];  r4 = (const float*)d_in[8];  r5 = (const float*)d_in[9];
        t3 = (const float*)d_in[10]; t4 = (const float*)d_in[11]; t5 = (const float*)d_in[12];
    }

    float* out       = (float*)d_out;
    float* out_dets  = out;                                   // [16,1000,5]
    float* out_delta = out + (size_t)BATCH * TOPK * 5;        // [16,21504,4]
    float* out_ctr   = out_delta + (size_t)BATCH * NTOT * 4;  // [16,21504]

    const int post_smem = 169088;
    cudaFuncSetAttribute(k_post, cudaFuncAttributeMaxDynamicSharedMemorySize, post_smem);

    dim3 grd(NTOT / 256, BATCH);
    k_fused<<<grd, 256>>>(l3, l4, l5, gt, c3, c4, c5, r3, r4, r5, t3, t4, t5,
                          (float4*)out_delta, out_ctr);
    k_post <<<BATCH, 1024, post_smem>>>(out_dets);
}